// round 5
// baseline (speedup 1.0000x reference)
#include <cuda_runtime.h>

#define NROWS 32768
#define DIM   128
#define NC    512
#define TOPK  10
#define MTILE 32
#define KT    32
#define CS_STRIDE 520      // padded center tile row stride (floats)
#define CAND_STRIDE 81     // padded candidate row stride (u64 keys)

// smem layout offsets (bytes)
#define OFF_CS    0
#define OFF_XS2   66560                 // 32*520*4
#define OFF_C2S   (OFF_XS2 + 8192)      // 32*32*8
#define OFF_X2S   (OFF_C2S + 2048)
#define OFF_CAND  (OFF_X2S + 128)
#define OFF_FIDX  (OFF_CAND + 20736)    // 32*81*8
#define SMEM_TOTAL (OFF_FIDX + 1280)    // 98944

__device__ float g_c2[NC];

// XLA GPU row-reduction for sum(v*v), 128-wide f32 row:
// single pass, 16-byte vectorized: lane t owns contiguous quad v[4t..4t+3],
// left-fold into scalar partial, then shfl_down tree offsets 16,8,4,2,1.
__device__ __forceinline__ float xla_row_sumsq(const float* __restrict__ row, int lane) {
    float4 v = *reinterpret_cast<const float4*>(row + 4 * lane);
    float p = __fmul_rn(v.x, v.x);
    p = __fadd_rn(p, __fmul_rn(v.y, v.y));
    p = __fadd_rn(p, __fmul_rn(v.z, v.z));
    p = __fadd_rn(p, __fmul_rn(v.w, v.w));
#pragma unroll
    for (int off = 16; off > 0; off >>= 1)
        p = __fadd_rn(p, __shfl_down_sync(0xffffffffu, p, off));
    return __shfl_sync(0xffffffffu, p, 0);
}

__global__ void c2_kernel(const float* __restrict__ cc) {
    int warp = threadIdx.x >> 5;
    int lane = threadIdx.x & 31;
    int c = blockIdx.x * 8 + warp;
    float s = xla_row_sumsq(cc + (size_t)c * DIM, lane);
    if (lane == 0) g_c2[c] = s;
}

__device__ __forceinline__ unsigned long long fma2(unsigned long long a,
                                                   unsigned long long b,
                                                   unsigned long long c) {
    unsigned long long d;
    asm("fma.rn.f32x2 %0, %1, %2, %3;" : "=l"(d) : "l"(a), "l"(b), "l"(c));
    return d;
}
__device__ __forceinline__ void unpack2(unsigned long long v, float& lo, float& hi) {
    asm("mov.b64 {%0, %1}, %2;" : "=f"(lo), "=f"(hi) : "l"(v));
}

__global__ __launch_bounds__(256, 2)
void kmeans_topk_kernel(const float* __restrict__ x,
                        const float* __restrict__ cc,
                        float* __restrict__ out) {
    extern __shared__ char smraw[];
    float*  cs    = reinterpret_cast<float*>(smraw + OFF_CS);     // [KT][CS_STRIDE]
    float2* xs2   = reinterpret_cast<float2*>(smraw + OFF_XS2);   // [KT][MTILE] duplicated x
    float*  c2s   = reinterpret_cast<float*>(smraw + OFF_C2S);    // [NC]
    float*  x2s   = reinterpret_cast<float*>(smraw + OFF_X2S);    // [MTILE]
    unsigned long long* cand =
        reinterpret_cast<unsigned long long*>(smraw + OFF_CAND);  // [MTILE][CAND_STRIDE]
    int*    fidx  = reinterpret_cast<int*>(smraw + OFF_FIDX);     // [MTILE][10]
    float*  score = cs;                                           // overlay [MTILE][NC] dists

    const int tx   = threadIdx.x;
    const int row0 = blockIdx.x * MTILE;
    const int lane = tx & 31;
    const int warp = tx >> 5;
    const int rg   = warp >> 1;        // 0..3 row groups (8 rows each)
    const int cgrp = warp & 1;         // 0..1 center half (256 each)
    const int rbase = rg * 8;
    const int cbase = cgrp * 256 + lane * 2;  // lane owns centers cbase+64j, +1

    for (int i = tx; i < NC; i += 256) c2s[i] = g_c2[i];

    // x2[row] with exact XLA GPU row-reduce order; warp w does rows w, w+8, w+16, w+24
#pragma unroll
    for (int j = 0; j < 4; ++j) {
        int rl = warp + 8 * j;
        float s = xla_row_sumsq(x + (size_t)(row0 + rl) * DIM, lane);
        if (lane == 0) x2s[rl] = s;
    }

    unsigned long long acc[8][4];
#pragma unroll
    for (int r = 0; r < 8; ++r)
#pragma unroll
        for (int j = 0; j < 4; ++j) acc[r][j] = 0ull;

    for (int kt = 0; kt < DIM; kt += KT) {
        __syncthreads();
        // ---- load center chunk transposed: cs[kk][c] = cc[c][kt+kk] ----
#pragma unroll
        for (int j = 0; j < 16; ++j) {
            int i = tx + 256 * j;
            int c = i & (NC - 1);
            int q = i >> 9;  // 0..7
            float4 v = *reinterpret_cast<const float4*>(cc + (size_t)c * DIM + kt + q * 4);
            cs[(q * 4 + 0) * CS_STRIDE + c] = v.x;
            cs[(q * 4 + 1) * CS_STRIDE + c] = v.y;
            cs[(q * 4 + 2) * CS_STRIDE + c] = v.z;
            cs[(q * 4 + 3) * CS_STRIDE + c] = v.w;
        }
        // ---- load x chunk duplicated: xs2[kk][r] = (x,x) ----
        {
            int r = tx & 31;
            int q = tx >> 5;  // 0..7
            float4 v = *reinterpret_cast<const float4*>(x + (size_t)(row0 + r) * DIM + kt + q * 4);
            xs2[(q * 4 + 0) * MTILE + r] = make_float2(v.x, v.x);
            xs2[(q * 4 + 1) * MTILE + r] = make_float2(v.y, v.y);
            xs2[(q * 4 + 2) * MTILE + r] = make_float2(v.z, v.z);
            xs2[(q * 4 + 3) * MTILE + r] = make_float2(v.w, v.w);
        }
        __syncthreads();

        const int cb2 = cbase >> 1;  // in 8-byte units
        // strict sequential ascending-k FMA chain per (row, center) accumulator
        // (matches cublas sgemm per-element accumulation order)
#pragma unroll 8
        for (int kk = 0; kk < KT; ++kk) {
            const unsigned long long* crow =
                reinterpret_cast<const unsigned long long*>(cs + kk * CS_STRIDE);
            const unsigned long long* xrow =
                reinterpret_cast<const unsigned long long*>(xs2 + kk * MTILE);
            unsigned long long cf0 = crow[cb2];
            unsigned long long cf1 = crow[cb2 + 32];
            unsigned long long cf2 = crow[cb2 + 64];
            unsigned long long cf3 = crow[cb2 + 96];
#pragma unroll
            for (int r = 0; r < 8; ++r) {
                unsigned long long xv = xrow[rbase + r];
                acc[r][0] = fma2(xv, cf0, acc[r][0]);
                acc[r][1] = fma2(xv, cf1, acc[r][1]);
                acc[r][2] = fma2(xv, cf2, acc[r][2]);
                acc[r][3] = fma2(xv, cf3, acc[r][3]);
            }
        }
    }
    __syncthreads();

    // ---- scores: dist = sqrt(max((x2 - 2*dot) + c2, 0)) with exact ref rounding ----
#pragma unroll
    for (int r = 0; r < 8; ++r) {
        int rl = rbase + r;
        float x2v = x2s[rl];
#pragma unroll
        for (int j = 0; j < 4; ++j) {
            int c0 = cbase + 64 * j;
            float lo, hi;
            unpack2(acc[r][j], lo, hi);
            float u0 = __fadd_rn(__fsub_rn(x2v, 2.0f * lo), c2s[c0]);
            float u1 = __fadd_rn(__fsub_rn(x2v, 2.0f * hi), c2s[c0 + 1]);
            float d0 = __fsqrt_rn(fmaxf(u0, 0.0f));
            float d1 = __fsqrt_rn(fmaxf(u1, 0.0f));
            *reinterpret_cast<float2*>(&score[rl * NC + c0]) = make_float2(d0, d1);
        }
    }
    __syncthreads();

    // ---- per-row local top-10 on packed keys (dist_bits<<32 | idx) ----
    {
        const int tsub = tx & 7;
        const int rl = tx >> 3;
        const int cb = tsub * 64;
        const int rot = tx & 63;  // bank-conflict-avoiding rotation (order-safe: keys)
        unsigned long long bs[TOPK];
#pragma unroll
        for (int p = 0; p < TOPK; ++p) bs[p] = ~0ull;
        for (int v = 0; v < 64; ++v) {
            int c = cb + ((v + rot) & 63);
            float s = score[rl * NC + c];
            unsigned long long key =
                ((unsigned long long)__float_as_uint(s) << 32) | (unsigned)c;
            if (key < bs[TOPK - 1]) {
                bs[TOPK - 1] = key;
#pragma unroll
                for (int p = TOPK - 1; p > 0; --p) {
                    if (bs[p] < bs[p - 1]) {
                        unsigned long long t = bs[p]; bs[p] = bs[p - 1]; bs[p - 1] = t;
                    }
                }
            }
        }
#pragma unroll
        for (int p = 0; p < TOPK; ++p)
            cand[rl * CAND_STRIDE + tsub * TOPK + p] = bs[p];
    }
    __syncthreads();

    // ---- merge 80 -> 10 per row ----
    if (tx < MTILE) {
        const int rl = tx;
        unsigned long long bs[TOPK];
#pragma unroll
        for (int p = 0; p < TOPK; ++p) bs[p] = ~0ull;
        for (int v = 0; v < 8 * TOPK; ++v) {
            unsigned long long key = cand[rl * CAND_STRIDE + v];
            if (key < bs[TOPK - 1]) {
                bs[TOPK - 1] = key;
#pragma unroll
                for (int p = TOPK - 1; p > 0; --p) {
                    if (bs[p] < bs[p - 1]) {
                        unsigned long long t = bs[p]; bs[p] = bs[p - 1]; bs[p - 1] = t;
                    }
                }
            }
        }
#pragma unroll
        for (int p = 0; p < TOPK; ++p)
            fidx[rl * TOPK + p] = (int)(unsigned)(bs[p] & 0xffffffffu);
    }
    __syncthreads();

    // ---- gather epilogue: out[row*10+t] = x[idx] (idx < 512 -> L2-hot) ----
    {
        const float4* x4 = reinterpret_cast<const float4*>(x);
        float4* out4 = reinterpret_cast<float4*>(out);
#pragma unroll
        for (int it = 0; it < 40; ++it) {
            int i = tx + 256 * it;          // 0 .. 10239
            int orow = i >> 5;              // 0 .. 319
            int e = i & 31;                 // float4 index within row
            int rl = orow / 10;
            int t = orow - rl * 10;
            int idx = fidx[rl * TOPK + t];
            size_t src = (size_t)idx * 32 + e;
            size_t dst = ((size_t)(row0 + rl) * 10 + t) * 32 + e;
            out4[dst] = __ldg(&x4[src]);
        }
    }
}

extern "C" void kernel_launch(void* const* d_in, const int* in_sizes, int n_in,
                              void* d_out, int out_size) {
    const float* x  = (const float*)d_in[0];
    const float* cc = (const float*)d_in[1];
    float* out = (float*)d_out;

    cudaFuncSetAttribute(kmeans_topk_kernel,
                         cudaFuncAttributeMaxDynamicSharedMemorySize, SMEM_TOTAL);
    c2_kernel<<<NC / 8, 256>>>(cc);
    kmeans_topk_kernel<<<NROWS / MTILE, 256, SMEM_TOTAL>>>(x, cc, out);
}